// round 4
// baseline (speedup 1.0000x reference)
#include <cuda_runtime.h>

#define DM   512
#define NH   4
#define HD   128
#define NB   2
#define SEQ  4096
#define MROWS (NB * SEQ)   // 8192
#define ATTN_SMEM ((128*68 + 128*68 + 64*128 + 64*68) * 4)  // 119808 bytes

// Scratch (no allocations allowed)
__device__ float g_Q[NB * NH * SEQ * HD];   // [b][h][s][d]
__device__ float g_K[NB * NH * SEQ * HD];
__device__ float g_V[NB * NH * SEQ * HD];
__device__ float g_A[MROWS * DM];           // attention out, [b][s][h*hd]

// ---------------------------------------------------------------------------
// Projection GEMM: C[M=8192, N=512] = X @ W^T + bias
// MODE 0/1/2 -> write split-head layout into g_Q/g_K/g_V
// MODE 3     -> X is g_A, write flat to outp (final output)
// BM=BN=64, BK=16, 256 threads, 4x4 micro-tile per thread.
// ---------------------------------------------------------------------------
template <int MODE>
__global__ __launch_bounds__(256) void proj_gemm(
    const float* __restrict__ Xin, const float* __restrict__ W,
    const float* __restrict__ bias, float* __restrict__ outp)
{
    __shared__ float As[16][68];   // k-major: As[k][m]
    __shared__ float Bs[16][68];   // k-major: Bs[k][n]

    const float* X = (MODE == 3) ? g_A : Xin;

    const int m0 = blockIdx.x * 64;
    const int n0 = blockIdx.y * 64;
    const int tid = threadIdx.x;
    const int tx = tid & 15, ty = tid >> 4;
    const int lk = tid & 15, lm = tid >> 4;

    float acc[4][4] = {};

    for (int k0 = 0; k0 < DM; k0 += 16) {
#pragma unroll
        for (int p = 0; p < 4; p++) {
            int m = lm + p * 16;
            As[lk][m] = X[(size_t)(m0 + m) * DM + k0 + lk];
            Bs[lk][m] = W[(size_t)(n0 + m) * DM + k0 + lk];
        }
        __syncthreads();
#pragma unroll
        for (int k = 0; k < 16; k++) {
            float4 a = *(const float4*)&As[k][ty * 4];
            float4 b = *(const float4*)&Bs[k][tx * 4];
            acc[0][0] += a.x * b.x; acc[0][1] += a.x * b.y; acc[0][2] += a.x * b.z; acc[0][3] += a.x * b.w;
            acc[1][0] += a.y * b.x; acc[1][1] += a.y * b.y; acc[1][2] += a.y * b.z; acc[1][3] += a.y * b.w;
            acc[2][0] += a.z * b.x; acc[2][1] += a.z * b.y; acc[2][2] += a.z * b.z; acc[2][3] += a.z * b.w;
            acc[3][0] += a.w * b.x; acc[3][1] += a.w * b.y; acc[3][2] += a.w * b.z; acc[3][3] += a.w * b.w;
        }
        __syncthreads();
    }

    float* dst;
    if (MODE == 0) dst = g_Q;
    else if (MODE == 1) dst = g_K;
    else if (MODE == 2) dst = g_V;
    else dst = outp;

#pragma unroll
    for (int i = 0; i < 4; i++) {
        int r = m0 + ty * 4 + i;
#pragma unroll
        for (int j = 0; j < 4; j++) {
            int c = n0 + tx * 4 + j;
            float v = acc[i][j] + bias[c];
            if (MODE == 3) {
                dst[(size_t)r * DM + c] = v;
            } else {
                int b = r >> 12, s = r & (SEQ - 1);
                int h = c >> 7,  d = c & (HD - 1);
                dst[(((size_t)(b * NH + h)) * SEQ + s) * HD + d] = v;
            }
        }
    }
}

// ---------------------------------------------------------------------------
// Flash attention: per (b,h), 64-query tile per CTA, iterate 64-key tiles.
// 256 threads as 16x16; each thread owns 4 rows x (4 score cols / 8 out cols).
// ---------------------------------------------------------------------------
__global__ __launch_bounds__(256) void flash_attn()
{
    extern __shared__ float sm[];
    float* Qs = sm;                     // [128][68]  d-major (pre-scaled)
    float* Ks = Qs + 128 * 68;          // [128][68]  d-major
    float* Vs = Ks + 128 * 68;          // [64][128]  row-major
    float* Ps = Vs + 64 * 128;          // [64][68]   row-major

    const int bh = blockIdx.y;          // 0..7
    const int q0 = blockIdx.x * 64;
    const int tid = threadIdx.x;
    const int tx = tid & 15, ty = tid >> 4;
    const float scale = 0.08838834764831845f;  // 1/sqrt(128)

    const float* Qg = g_Q + (size_t)bh * SEQ * HD;
    const float* Kg = g_K + (size_t)bh * SEQ * HD;
    const float* Vg = g_V + (size_t)bh * SEQ * HD;

    {
        const int d = tid & 127, r0 = tid >> 7;
#pragma unroll
        for (int p = 0; p < 32; p++) {
            int r = r0 + p * 2;
            Qs[d * 68 + r] = Qg[(size_t)(q0 + r) * HD + d] * scale;
        }
    }

    float m_run[4], l_run[4], o[4][8];
#pragma unroll
    for (int i = 0; i < 4; i++) {
        m_run[i] = -1e30f; l_run[i] = 0.f;
#pragma unroll
        for (int j = 0; j < 8; j++) o[i][j] = 0.f;
    }

    for (int t = 0; t < SEQ / 64; t++) {
        const int k0 = t * 64;
        {
            const int d = tid & 127, r0 = tid >> 7;
#pragma unroll
            for (int p = 0; p < 32; p++) {
                int c = r0 + p * 2;
                float kv = Kg[(size_t)(k0 + c) * HD + d];
                float vv = Vg[(size_t)(k0 + c) * HD + d];
                Ks[d * 68 + c] = kv;
                Vs[c * 128 + d] = vv;
            }
        }
        __syncthreads();

        // S = (Q*scale) K^T : 4x4 per thread
        float s0[4][4] = {};
#pragma unroll 4
        for (int d = 0; d < 128; d++) {
            float4 a = *(const float4*)&Qs[d * 68 + ty * 4];
            float4 b = *(const float4*)&Ks[d * 68 + tx * 4];
            s0[0][0] += a.x * b.x; s0[0][1] += a.x * b.y; s0[0][2] += a.x * b.z; s0[0][3] += a.x * b.w;
            s0[1][0] += a.y * b.x; s0[1][1] += a.y * b.y; s0[1][2] += a.y * b.z; s0[1][3] += a.y * b.w;
            s0[2][0] += a.z * b.x; s0[2][1] += a.z * b.y; s0[2][2] += a.z * b.z; s0[2][3] += a.z * b.w;
            s0[3][0] += a.w * b.x; s0[3][1] += a.w * b.y; s0[3][2] += a.w * b.z; s0[3][3] += a.w * b.w;
        }

        // online softmax update (row reductions across the 16 tx lanes)
#pragma unroll
        for (int i = 0; i < 4; i++) {
            float tm = fmaxf(fmaxf(s0[i][0], s0[i][1]), fmaxf(s0[i][2], s0[i][3]));
#pragma unroll
            for (int msk = 8; msk > 0; msk >>= 1)
                tm = fmaxf(tm, __shfl_xor_sync(0xffffffffu, tm, msk));
            float mn = fmaxf(m_run[i], tm);
            float alpha = __expf(m_run[i] - mn);
            float4 pv;
            pv.x = __expf(s0[i][0] - mn);
            pv.y = __expf(s0[i][1] - mn);
            pv.z = __expf(s0[i][2] - mn);
            pv.w = __expf(s0[i][3] - mn);
            float ps = pv.x + pv.y + pv.z + pv.w;
#pragma unroll
            for (int msk = 8; msk > 0; msk >>= 1)
                ps += __shfl_xor_sync(0xffffffffu, ps, msk);
            l_run[i] = l_run[i] * alpha + ps;
            m_run[i] = mn;
#pragma unroll
            for (int j = 0; j < 8; j++) o[i][j] *= alpha;
            *(float4*)&Ps[(ty * 4 + i) * 68 + tx * 4] = pv;
        }
        __syncthreads();

        // O += P V : each thread 4 rows x 8 dims
#pragma unroll 2
        for (int c = 0; c < 64; c++) {
            float4 v0 = *(const float4*)&Vs[c * 128 + tx * 8];
            float4 v1 = *(const float4*)&Vs[c * 128 + tx * 8 + 4];
#pragma unroll
            for (int i = 0; i < 4; i++) {
                float p = Ps[(ty * 4 + i) * 68 + c];
                o[i][0] += p * v0.x; o[i][1] += p * v0.y; o[i][2] += p * v0.z; o[i][3] += p * v0.w;
                o[i][4] += p * v1.x; o[i][5] += p * v1.y; o[i][6] += p * v1.z; o[i][7] += p * v1.w;
            }
        }
        __syncthreads();
    }

    const int b = bh >> 2, h = bh & 3;
#pragma unroll
    for (int i = 0; i < 4; i++) {
        int r = q0 + ty * 4 + i;
        float inv = 1.0f / l_run[i];
        float4 w0, w1;
        w0.x = o[i][0] * inv; w0.y = o[i][1] * inv; w0.z = o[i][2] * inv; w0.w = o[i][3] * inv;
        w1.x = o[i][4] * inv; w1.y = o[i][5] * inv; w1.z = o[i][6] * inv; w1.w = o[i][7] * inv;
        float* dst = g_A + ((size_t)(b * SEQ + r)) * DM + h * HD + tx * 8;
        *(float4*)dst = w0;
        *(float4*)(dst + 4) = w1;
    }
}

// ---------------------------------------------------------------------------
extern "C" void kernel_launch(void* const* d_in, const int* in_sizes, int n_in,
                              void* d_out, int out_size)
{
    const float* query = (const float*)d_in[0];
    const float* key   = (const float*)d_in[1];
    const float* value = (const float*)d_in[2];
    const float* Wq = (const float*)d_in[3];
    const float* bq = (const float*)d_in[4];
    const float* Wk = (const float*)d_in[5];
    const float* bk = (const float*)d_in[6];
    const float* Wv = (const float*)d_in[7];
    const float* bv = (const float*)d_in[8];
    const float* Wo = (const float*)d_in[9];
    const float* bo = (const float*)d_in[10];
    float* out = (float*)d_out;

    (void)cudaFuncSetAttribute(flash_attn,
                               cudaFuncAttributeMaxDynamicSharedMemorySize,
                               ATTN_SMEM);

    dim3 blk(256);
    dim3 gp(MROWS / 64, DM / 64);        // 128 x 8
    proj_gemm<0><<<gp, blk>>>(query, Wq, bq, nullptr);
    proj_gemm<1><<<gp, blk>>>(key,   Wk, bk, nullptr);
    proj_gemm<2><<<gp, blk>>>(value, Wv, bv, nullptr);

    dim3 ga(SEQ / 64, NB * NH);          // 64 x 8
    flash_attn<<<ga, blk, ATTN_SMEM>>>();

    proj_gemm<3><<<gp, blk>>>(nullptr, Wo, bo, out);
}

// round 10
// speedup vs baseline: 3.0994x; 3.0994x over previous
#include <cuda_runtime.h>
#include <cstdint>

#define DM   512
#define NH   4
#define HD   128
#define NB   2
#define SEQ  4096
#define MROWS (NB * SEQ)   // 8192

// Scratch (no allocations allowed)
__device__ float g_Q[NB * NH * SEQ * HD];   // [b][h][s][d]
__device__ float g_K[NB * NH * SEQ * HD];   // [b][h][s][d]
__device__ float g_V[NB * NH * SEQ * HD];   // [b][h][s][d]
__device__ float g_A[MROWS * DM];           // attention out, [b][s][h*hd]

// ---------------------------------------------------------------------------
// tf32 helpers (legacy warp-level tensor path — works on plain sm_103 target)
// ---------------------------------------------------------------------------
__device__ __forceinline__ uint32_t f2tf32(float f) {
    uint32_t r;
    asm("cvt.rna.tf32.f32 %0, %1;" : "=r"(r) : "f"(f));
    return r;
}

// D(16x8,f32) += A(16x8,tf32,row) @ B(8x8,tf32,col)
__device__ __forceinline__ void mma_tf32(float* c, const uint32_t* a,
                                         uint32_t b0, uint32_t b1) {
    asm volatile(
        "mma.sync.aligned.m16n8k8.row.col.f32.tf32.tf32.f32 "
        "{%0,%1,%2,%3}, {%4,%5,%6,%7}, {%8,%9}, {%0,%1,%2,%3};"
        : "+f"(c[0]), "+f"(c[1]), "+f"(c[2]), "+f"(c[3])
        : "r"(a[0]), "r"(a[1]), "r"(a[2]), "r"(a[3]), "r"(b0), "r"(b1));
}

// ---------------------------------------------------------------------------
// Projection GEMM (fp32 SIMT): C[8192,512] = X @ W^T + bias
// MODE 0/1/2 -> g_Q/g_K/g_V split-head [b][h][s][d]; MODE 3 -> X=g_A, flat.
// ---------------------------------------------------------------------------
template <int MODE>
__global__ __launch_bounds__(256) void proj_gemm(
    const float* __restrict__ Xin, const float* __restrict__ W,
    const float* __restrict__ bias, float* __restrict__ outp)
{
    __shared__ float As[16][68];
    __shared__ float Bs[16][68];

    const float* X = (MODE == 3) ? g_A : Xin;

    const int m0 = blockIdx.x * 64;
    const int n0 = blockIdx.y * 64;
    const int tid = threadIdx.x;
    const int tx = tid & 15, ty = tid >> 4;
    const int lk = tid & 15, lm = tid >> 4;

    float acc[4][4] = {};

    for (int k0 = 0; k0 < DM; k0 += 16) {
#pragma unroll
        for (int p = 0; p < 4; p++) {
            int m = lm + p * 16;
            As[lk][m] = X[(size_t)(m0 + m) * DM + k0 + lk];
            Bs[lk][m] = W[(size_t)(n0 + m) * DM + k0 + lk];
        }
        __syncthreads();
#pragma unroll
        for (int k = 0; k < 16; k++) {
            float4 a = *(const float4*)&As[k][ty * 4];
            float4 b = *(const float4*)&Bs[k][tx * 4];
            acc[0][0] += a.x * b.x; acc[0][1] += a.x * b.y; acc[0][2] += a.x * b.z; acc[0][3] += a.x * b.w;
            acc[1][0] += a.y * b.x; acc[1][1] += a.y * b.y; acc[1][2] += a.y * b.z; acc[1][3] += a.y * b.w;
            acc[2][0] += a.z * b.x; acc[2][1] += a.z * b.y; acc[2][2] += a.z * b.z; acc[2][3] += a.z * b.w;
            acc[3][0] += a.w * b.x; acc[3][1] += a.w * b.y; acc[3][2] += a.w * b.z; acc[3][3] += a.w * b.w;
        }
        __syncthreads();
    }

    float* dst;
    if (MODE == 0) dst = g_Q;
    else if (MODE == 1) dst = g_K;
    else if (MODE == 2) dst = g_V;
    else dst = outp;

#pragma unroll
    for (int i = 0; i < 4; i++) {
        int r = m0 + ty * 4 + i;
#pragma unroll
        for (int j = 0; j < 4; j++) {
            int c = n0 + tx * 4 + j;
            float v = acc[i][j] + bias[c];
            if (MODE == 3) {
                dst[(size_t)r * DM + c] = v;
            } else {
                int b = r >> 12, s = r & (SEQ - 1);
                int h = c >> 7,  d = c & (HD - 1);
                dst[(((size_t)(b * NH + h)) * SEQ + s) * HD + d] = v;
            }
        }
    }
}

// ---------------------------------------------------------------------------
// Flash attention on legacy tensor cores (mma.sync m16n8k8 tf32).
// CTA: 256 threads (8 warps), 128 q-rows (16 per warp), 128-key tiles.
// Q fragments live in registers for the whole kernel. K/V staged to smem
// (tf32-converted, padded strides: K 132, V 136 -> conflict-free B-frag reads).
// Softmax in registers on C-fragments (quad shfl reductions); P goes through
// per-warp private smem (no barrier needed) and is re-read as A-fragments.
// ---------------------------------------------------------------------------
#define KSTR 132
#define VSTR 136
#define PSTR 132
#define SM_K_WORDS (128 * KSTR)              // 16896
#define SM_V_WORDS (128 * VSTR)              // 17408
#define SM_P_WORDS (16 * PSTR)               // per warp: 2112
#define FLASH_SMEM ((SM_K_WORDS + SM_V_WORDS + 8 * SM_P_WORDS) * 4)  // 204800 B

__global__ __launch_bounds__(256, 1) void flash_attn_mma()
{
    extern __shared__ uint32_t smw[];
    uint32_t* sK = smw;                       // [key][d]   tf32, stride 132
    uint32_t* sV = sK + SM_K_WORDS;           // [key][d]   tf32, stride 136
    uint32_t* sP = sV + SM_V_WORDS;           // 8 x [16][PSTR] tf32 (per warp)

    const int tid  = threadIdx.x;
    const int wq   = tid >> 5;                // warp id 0..7
    const int lane = tid & 31;
    const int gid  = lane >> 2;               // 0..7
    const int tig  = lane & 3;                // 0..3
    const int bh = blockIdx.y;
    const int q0 = blockIdx.x * 128;
    const float scale = 0.08838834764831845f; // 1/sqrt(128)

    const float* Qg = g_Q + (size_t)bh * SEQ * HD;
    const float* Kg = g_K + (size_t)bh * SEQ * HD;
    const float* Vg = g_V + (size_t)bh * SEQ * HD;

    // Q fragments (row-major A): rows q0+wq*16+{gid,gid+8}, 16 k-steps over d.
    uint32_t qa[16][4];
    {
        const float* qr0 = Qg + (size_t)(q0 + wq * 16 + gid) * HD;
        const float* qr1 = qr0 + 8 * HD;
#pragma unroll
        for (int kk = 0; kk < 16; kk++) {
            qa[kk][0] = f2tf32(qr0[kk * 8 + tig] * scale);
            qa[kk][1] = f2tf32(qr1[kk * 8 + tig] * scale);
            qa[kk][2] = f2tf32(qr0[kk * 8 + tig + 4] * scale);
            qa[kk][3] = f2tf32(qr1[kk * 8 + tig + 4] * scale);
        }
    }

    uint32_t* sPw = sP + wq * SM_P_WORDS;

    float oacc[16][4];
#pragma unroll
    for (int n = 0; n < 16; n++)
#pragma unroll
        for (int j = 0; j < 4; j++) oacc[n][j] = 0.f;
    float m0 = -1e30f, m1 = -1e30f, l0 = 0.f, l1 = 0.f;

    for (int t = 0; t < SEQ / 128; t++) {
        const int k0 = t * 128;

        // ---- stage K,V tile (tf32-converted) ----
        if (t > 0) __syncthreads();           // all warps done with prev K/V
#pragma unroll
        for (int i = 0; i < 16; i++) {
            int r = i * 8 + wq;
            float4 kv = *(const float4*)&Kg[(size_t)(k0 + r) * HD + lane * 4];
            uint32_t* dk = sK + r * KSTR + lane * 4;
            dk[0] = f2tf32(kv.x); dk[1] = f2tf32(kv.y);
            dk[2] = f2tf32(kv.z); dk[3] = f2tf32(kv.w);
            float4 vv = *(const float4*)&Vg[(size_t)(k0 + r) * HD + lane * 4];
            uint32_t* dv = sV + r * VSTR + lane * 4;
            dv[0] = f2tf32(vv.x); dv[1] = f2tf32(vv.y);
            dv[2] = f2tf32(vv.z); dv[3] = f2tf32(vv.w);
        }
        __syncthreads();

        // ---- S = Q @ K^T  (16 n-chunks of 8 keys, 16 k-steps over d) ----
        float sacc[16][4];
#pragma unroll
        for (int n = 0; n < 16; n++) {
            sacc[n][0] = sacc[n][1] = sacc[n][2] = sacc[n][3] = 0.f;
            const uint32_t* kb = sK + (n * 8 + gid) * KSTR;
#pragma unroll
            for (int kk = 0; kk < 16; kk++)
                mma_tf32(sacc[n], qa[kk], kb[kk * 8 + tig], kb[kk * 8 + tig + 4]);
        }

        // ---- online softmax (rows gid and gid+8 of this warp's 16) ----
        float mx0 = m0, mx1 = m1;
#pragma unroll
        for (int n = 0; n < 16; n++) {
            mx0 = fmaxf(mx0, fmaxf(sacc[n][0], sacc[n][1]));
            mx1 = fmaxf(mx1, fmaxf(sacc[n][2], sacc[n][3]));
        }
        mx0 = fmaxf(mx0, __shfl_xor_sync(0xffffffffu, mx0, 1));
        mx0 = fmaxf(mx0, __shfl_xor_sync(0xffffffffu, mx0, 2));
        mx1 = fmaxf(mx1, __shfl_xor_sync(0xffffffffu, mx1, 1));
        mx1 = fmaxf(mx1, __shfl_xor_sync(0xffffffffu, mx1, 2));

        const float alpha0 = __expf(m0 - mx0);
        const float alpha1 = __expf(m1 - mx1);
        m0 = mx0; m1 = mx1;

        float sum0 = 0.f, sum1 = 0.f;
#pragma unroll
        for (int n = 0; n < 16; n++) {
            float p00 = __expf(sacc[n][0] - mx0);
            float p01 = __expf(sacc[n][1] - mx0);
            float p10 = __expf(sacc[n][2] - mx1);
            float p11 = __expf(sacc[n][3] - mx1);
            sum0 += p00 + p01;
            sum1 += p10 + p11;
            uint2 w0; w0.x = f2tf32(p00); w0.y = f2tf32(p01);
            uint2 w1; w1.x = f2tf32(p10); w1.y = f2tf32(p11);
            *(uint2*)&sPw[gid * PSTR + n * 8 + 2 * tig] = w0;
            *(uint2*)&sPw[(gid + 8) * PSTR + n * 8 + 2 * tig] = w1;
        }
        sum0 += __shfl_xor_sync(0xffffffffu, sum0, 1);
        sum0 += __shfl_xor_sync(0xffffffffu, sum0, 2);
        sum1 += __shfl_xor_sync(0xffffffffu, sum1, 1);
        sum1 += __shfl_xor_sync(0xffffffffu, sum1, 2);
        l0 = l0 * alpha0 + sum0;
        l1 = l1 * alpha1 + sum1;

        // rescale O
#pragma unroll
        for (int n = 0; n < 16; n++) {
            oacc[n][0] *= alpha0; oacc[n][1] *= alpha0;
            oacc[n][2] *= alpha1; oacc[n][3] *= alpha1;
        }
        __syncwarp();                          // P visible within warp

        // ---- O += P @ V  (A = P from per-warp smem, B = V) ----
#pragma unroll
        for (int kk = 0; kk < 16; kk++) {
            uint32_t pa[4];
            pa[0] = sPw[gid * PSTR + kk * 8 + tig];
            pa[1] = sPw[(gid + 8) * PSTR + kk * 8 + tig];
            pa[2] = sPw[gid * PSTR + kk * 8 + tig + 4];
            pa[3] = sPw[(gid + 8) * PSTR + kk * 8 + tig + 4];
            const uint32_t* vb0 = sV + (kk * 8 + tig) * VSTR;
            const uint32_t* vb1 = sV + (kk * 8 + tig + 4) * VSTR;
#pragma unroll
            for (int n = 0; n < 16; n++)
                mma_tf32(oacc[n], pa, vb0[n * 8 + gid], vb1[n * 8 + gid]);
        }
    }

    // ---- epilogue: normalize and write to g_A ----
    const int b = bh >> 2, h = bh & 3;
    const float inv0 = 1.0f / l0, inv1 = 1.0f / l1;
    float* a0 = g_A + (size_t)(b * SEQ + q0 + wq * 16 + gid) * DM + h * HD;
    float* a1 = a0 + 8 * DM;
#pragma unroll
    for (int n = 0; n < 16; n++) {
        float2 w0; w0.x = oacc[n][0] * inv0; w0.y = oacc[n][1] * inv0;
        float2 w1; w1.x = oacc[n][2] * inv1; w1.y = oacc[n][3] * inv1;
        *(float2*)&a0[n * 8 + 2 * tig] = w0;
        *(float2*)&a1[n * 8 + 2 * tig] = w1;
    }
}

// ---------------------------------------------------------------------------
extern "C" void kernel_launch(void* const* d_in, const int* in_sizes, int n_in,
                              void* d_out, int out_size)
{
    const float* query = (const float*)d_in[0];
    const float* key   = (const float*)d_in[1];
    const float* value = (const float*)d_in[2];
    const float* Wq = (const float*)d_in[3];
    const float* bq = (const float*)d_in[4];
    const float* Wk = (const float*)d_in[5];
    const float* bk = (const float*)d_in[6];
    const float* Wv = (const float*)d_in[7];
    const float* bv = (const float*)d_in[8];
    const float* Wo = (const float*)d_in[9];
    const float* bo = (const float*)d_in[10];
    float* out = (float*)d_out;

    (void)cudaFuncSetAttribute(flash_attn_mma,
                               cudaFuncAttributeMaxDynamicSharedMemorySize,
                               FLASH_SMEM);

    dim3 blk(256);
    dim3 gp(MROWS / 64, DM / 64);        // 128 x 8
    proj_gemm<0><<<gp, blk>>>(query, Wq, bq, nullptr);
    proj_gemm<1><<<gp, blk>>>(key,   Wk, bk, nullptr);
    proj_gemm<2><<<gp, blk>>>(value, Wv, bv, nullptr);

    dim3 ga(SEQ / 128, NB * NH);         // 32 x 8
    flash_attn_mma<<<ga, blk, FLASH_SMEM>>>();

    proj_gemm<3><<<gp, blk>>>(nullptr, Wo, bo, out);
}

// round 11
// speedup vs baseline: 4.9285x; 1.5901x over previous
#include <cuda_runtime.h>
#include <cstdint>

#define DM   512
#define NH   4
#define HD   128
#define NB   2
#define SEQ  4096
#define MROWS (NB * SEQ)   // 8192

// Scratch (no allocations allowed)
__device__ float g_Q[NB * NH * SEQ * HD];   // [b][h][s][d]
__device__ float g_K[NB * NH * SEQ * HD];   // [b][h][s][d]
__device__ float g_V[NB * NH * SEQ * HD];   // [b][h][s][d]
__device__ float g_A[MROWS * DM];           // attention out, [b][s][h*hd]

// ---------------------------------------------------------------------------
// tf32 helpers (legacy warp-level tensor path — works on plain sm_103 target)
// ---------------------------------------------------------------------------
__device__ __forceinline__ uint32_t f2tf32(float f) {
    uint32_t r;
    asm("cvt.rna.tf32.f32 %0, %1;" : "=r"(r) : "f"(f));
    return r;
}

// D(16x8,f32) += A(16x8,tf32,row) @ B(8x8,tf32,col)
__device__ __forceinline__ void mma_tf32(float* c, const uint32_t* a,
                                         uint32_t b0, uint32_t b1) {
    asm volatile(
        "mma.sync.aligned.m16n8k8.row.col.f32.tf32.tf32.f32 "
        "{%0,%1,%2,%3}, {%4,%5,%6,%7}, {%8,%9}, {%0,%1,%2,%3};"
        : "+f"(c[0]), "+f"(c[1]), "+f"(c[2]), "+f"(c[3])
        : "r"(a[0]), "r"(a[1]), "r"(a[2]), "r"(a[3]), "r"(b0), "r"(b1));
}

// ---------------------------------------------------------------------------
// Tensor-core projection GEMM: C[8192,512] = X @ W^T + bias.
// CTA tile 128x128, BK=32, 256 threads = 8 warps (4m x 2n), warp tile 32x64.
// smem stride 36 words -> conflict-free fragment loads.
// split=1: write split-head [b][h][s][d]; split=0: flat row-major.
// ---------------------------------------------------------------------------
__device__ __forceinline__ void gemm_tc_body(
    const float* __restrict__ X, const float* __restrict__ W,
    const float* __restrict__ bias, float* __restrict__ dst, int split,
    uint32_t* sX, uint32_t* sW)
{
    const int m0 = blockIdx.x * 128;
    const int n0 = blockIdx.y * 128;
    const int tid = threadIdx.x;
    const int w = tid >> 5, lane = tid & 31;
    const int gid = lane >> 2, tig = lane & 3;
    const int mw = (w >> 1) * 32;          // warp m offset within tile
    const int nw = (w & 1) * 64;           // warp n offset within tile

    float acc[2][8][4];
#pragma unroll
    for (int mi = 0; mi < 2; mi++)
#pragma unroll
        for (int ni = 0; ni < 8; ni++)
#pragma unroll
            for (int j = 0; j < 4; j++) acc[mi][ni][j] = 0.f;

    for (int k0 = 0; k0 < DM; k0 += 32) {
        if (k0) __syncthreads();
        // stage X[128][32] and W[128][32] as tf32, stride 36
#pragma unroll
        for (int i = 0; i < 4; i++) {
            int idx = tid + i * 256;               // float4 id, 1024 total
            int row = idx >> 3, c4 = (idx & 7) * 4;
            float4 xv = *(const float4*)&X[(size_t)(m0 + row) * DM + k0 + c4];
            uint4 tx;
            tx.x = f2tf32(xv.x); tx.y = f2tf32(xv.y);
            tx.z = f2tf32(xv.z); tx.w = f2tf32(xv.w);
            *(uint4*)(sX + row * 36 + c4) = tx;
            float4 wv = *(const float4*)&W[(size_t)(n0 + row) * DM + k0 + c4];
            uint4 tw;
            tw.x = f2tf32(wv.x); tw.y = f2tf32(wv.y);
            tw.z = f2tf32(wv.z); tw.w = f2tf32(wv.w);
            *(uint4*)(sW + row * 36 + c4) = tw;
        }
        __syncthreads();

#pragma unroll
        for (int kk = 0; kk < 4; kk++) {
            uint32_t a[2][4];
#pragma unroll
            for (int mi = 0; mi < 2; mi++) {
                const uint32_t* xr = sX + (mw + mi * 16 + gid) * 36 + kk * 8;
                a[mi][0] = xr[tig];
                a[mi][2] = xr[tig + 4];
                const uint32_t* xr2 = xr + 8 * 36;
                a[mi][1] = xr2[tig];
                a[mi][3] = xr2[tig + 4];
            }
#pragma unroll
            for (int ni = 0; ni < 8; ni++) {
                const uint32_t* wr = sW + (nw + ni * 8 + gid) * 36 + kk * 8;
                uint32_t b0 = wr[tig], b1 = wr[tig + 4];
                mma_tf32(acc[0][ni], a[0], b0, b1);
                mma_tf32(acc[1][ni], a[1], b0, b1);
            }
        }
    }

    // epilogue: C rows gid / gid+8, cols 2tig / 2tig+1 per chunk
#pragma unroll
    for (int mi = 0; mi < 2; mi++) {
        int r0 = m0 + mw + mi * 16 + gid;
#pragma unroll
        for (int ni = 0; ni < 8; ni++) {
            int c = n0 + nw + ni * 8 + 2 * tig;
            float bx = bias[c], by = bias[c + 1];
            float2 v0 = make_float2(acc[mi][ni][0] + bx, acc[mi][ni][1] + by);
            float2 v1 = make_float2(acc[mi][ni][2] + bx, acc[mi][ni][3] + by);
            if (split) {
                int h = c >> 7, d = c & (HD - 1);
                int b0r = r0 >> 12, s0 = r0 & (SEQ - 1);
                *(float2*)&dst[(((size_t)(b0r * NH + h)) * SEQ + s0) * HD + d] = v0;
                int r1 = r0 + 8;
                int b1r = r1 >> 12, s1 = r1 & (SEQ - 1);
                *(float2*)&dst[(((size_t)(b1r * NH + h)) * SEQ + s1) * HD + d] = v1;
            } else {
                *(float2*)&dst[(size_t)r0 * DM + c] = v0;
                *(float2*)&dst[(size_t)(r0 + 8) * DM + c] = v1;
            }
        }
    }
}

__global__ __launch_bounds__(256, 2) void qkv_proj_tc(
    const float* __restrict__ q, const float* __restrict__ k,
    const float* __restrict__ v,
    const float* __restrict__ Wq, const float* __restrict__ bq,
    const float* __restrict__ Wk, const float* __restrict__ bk,
    const float* __restrict__ Wv, const float* __restrict__ bv)
{
    __shared__ __align__(16) uint32_t sX[128 * 36];
    __shared__ __align__(16) uint32_t sW[128 * 36];
    const int z = blockIdx.z;
    const float *X, *W, *B;
    float* dst;
    if (z == 0)      { X = q; W = Wq; B = bq; dst = g_Q; }
    else if (z == 1) { X = k; W = Wk; B = bk; dst = g_K; }
    else             { X = v; W = Wv; B = bv; dst = g_V; }
    gemm_tc_body(X, W, B, dst, 1, sX, sW);
}

__global__ __launch_bounds__(256, 2) void out_proj_tc(
    const float* __restrict__ Wo, const float* __restrict__ bo,
    float* __restrict__ outp)
{
    __shared__ __align__(16) uint32_t sX[128 * 36];
    __shared__ __align__(16) uint32_t sW[128 * 36];
    gemm_tc_body(g_A, Wo, bo, outp, 0, sX, sW);
}

// ---------------------------------------------------------------------------
// Flash attention on legacy tensor cores (mma.sync m16n8k8 tf32).
// (UNCHANGED from round 10 — proven at 600us / rel_err 5.9e-5.)
// ---------------------------------------------------------------------------
#define KSTR 132
#define VSTR 136
#define PSTR 132
#define SM_K_WORDS (128 * KSTR)              // 16896
#define SM_V_WORDS (128 * VSTR)              // 17408
#define SM_P_WORDS (16 * PSTR)               // per warp: 2112
#define FLASH_SMEM ((SM_K_WORDS + SM_V_WORDS + 8 * SM_P_WORDS) * 4)  // 204800 B

__global__ __launch_bounds__(256, 1) void flash_attn_mma()
{
    extern __shared__ uint32_t smw[];
    uint32_t* sK = smw;                       // [key][d]   tf32, stride 132
    uint32_t* sV = sK + SM_K_WORDS;           // [key][d]   tf32, stride 136
    uint32_t* sP = sV + SM_V_WORDS;           // 8 x [16][PSTR] tf32 (per warp)

    const int tid  = threadIdx.x;
    const int wq   = tid >> 5;                // warp id 0..7
    const int lane = tid & 31;
    const int gid  = lane >> 2;               // 0..7
    const int tig  = lane & 3;                // 0..3
    const int bh = blockIdx.y;
    const int q0 = blockIdx.x * 128;
    const float scale = 0.08838834764831845f; // 1/sqrt(128)

    const float* Qg = g_Q + (size_t)bh * SEQ * HD;
    const float* Kg = g_K + (size_t)bh * SEQ * HD;
    const float* Vg = g_V + (size_t)bh * SEQ * HD;

    // Q fragments (row-major A): rows q0+wq*16+{gid,gid+8}, 16 k-steps over d.
    uint32_t qa[16][4];
    {
        const float* qr0 = Qg + (size_t)(q0 + wq * 16 + gid) * HD;
        const float* qr1 = qr0 + 8 * HD;
#pragma unroll
        for (int kk = 0; kk < 16; kk++) {
            qa[kk][0] = f2tf32(qr0[kk * 8 + tig] * scale);
            qa[kk][1] = f2tf32(qr1[kk * 8 + tig] * scale);
            qa[kk][2] = f2tf32(qr0[kk * 8 + tig + 4] * scale);
            qa[kk][3] = f2tf32(qr1[kk * 8 + tig + 4] * scale);
        }
    }

    uint32_t* sPw = sP + wq * SM_P_WORDS;

    float oacc[16][4];
#pragma unroll
    for (int n = 0; n < 16; n++)
#pragma unroll
        for (int j = 0; j < 4; j++) oacc[n][j] = 0.f;
    float m0 = -1e30f, m1 = -1e30f, l0 = 0.f, l1 = 0.f;

    for (int t = 0; t < SEQ / 128; t++) {
        const int k0 = t * 128;

        // ---- stage K,V tile (tf32-converted) ----
        if (t > 0) __syncthreads();           // all warps done with prev K/V
#pragma unroll
        for (int i = 0; i < 16; i++) {
            int r = i * 8 + wq;
            float4 kv = *(const float4*)&Kg[(size_t)(k0 + r) * HD + lane * 4];
            uint32_t* dk = sK + r * KSTR + lane * 4;
            dk[0] = f2tf32(kv.x); dk[1] = f2tf32(kv.y);
            dk[2] = f2tf32(kv.z); dk[3] = f2tf32(kv.w);
            float4 vv = *(const float4*)&Vg[(size_t)(k0 + r) * HD + lane * 4];
            uint32_t* dv = sV + r * VSTR + lane * 4;
            dv[0] = f2tf32(vv.x); dv[1] = f2tf32(vv.y);
            dv[2] = f2tf32(vv.z); dv[3] = f2tf32(vv.w);
        }
        __syncthreads();

        // ---- S = Q @ K^T  (16 n-chunks of 8 keys, 16 k-steps over d) ----
        float sacc[16][4];
#pragma unroll
        for (int n = 0; n < 16; n++) {
            sacc[n][0] = sacc[n][1] = sacc[n][2] = sacc[n][3] = 0.f;
            const uint32_t* kb = sK + (n * 8 + gid) * KSTR;
#pragma unroll
            for (int kk = 0; kk < 16; kk++)
                mma_tf32(sacc[n], qa[kk], kb[kk * 8 + tig], kb[kk * 8 + tig + 4]);
        }

        // ---- online softmax (rows gid and gid+8 of this warp's 16) ----
        float mx0 = m0, mx1 = m1;
#pragma unroll
        for (int n = 0; n < 16; n++) {
            mx0 = fmaxf(mx0, fmaxf(sacc[n][0], sacc[n][1]));
            mx1 = fmaxf(mx1, fmaxf(sacc[n][2], sacc[n][3]));
        }
        mx0 = fmaxf(mx0, __shfl_xor_sync(0xffffffffu, mx0, 1));
        mx0 = fmaxf(mx0, __shfl_xor_sync(0xffffffffu, mx0, 2));
        mx1 = fmaxf(mx1, __shfl_xor_sync(0xffffffffu, mx1, 1));
        mx1 = fmaxf(mx1, __shfl_xor_sync(0xffffffffu, mx1, 2));

        const float alpha0 = __expf(m0 - mx0);
        const float alpha1 = __expf(m1 - mx1);
        m0 = mx0; m1 = mx1;

        float sum0 = 0.f, sum1 = 0.f;
#pragma unroll
        for (int n = 0; n < 16; n++) {
            float p00 = __expf(sacc[n][0] - mx0);
            float p01 = __expf(sacc[n][1] - mx0);
            float p10 = __expf(sacc[n][2] - mx1);
            float p11 = __expf(sacc[n][3] - mx1);
            sum0 += p00 + p01;
            sum1 += p10 + p11;
            uint2 w0; w0.x = f2tf32(p00); w0.y = f2tf32(p01);
            uint2 w1; w1.x = f2tf32(p10); w1.y = f2tf32(p11);
            *(uint2*)&sPw[gid * PSTR + n * 8 + 2 * tig] = w0;
            *(uint2*)&sPw[(gid + 8) * PSTR + n * 8 + 2 * tig] = w1;
        }
        sum0 += __shfl_xor_sync(0xffffffffu, sum0, 1);
        sum0 += __shfl_xor_sync(0xffffffffu, sum0, 2);
        sum1 += __shfl_xor_sync(0xffffffffu, sum1, 1);
        sum1 += __shfl_xor_sync(0xffffffffu, sum1, 2);
        l0 = l0 * alpha0 + sum0;
        l1 = l1 * alpha1 + sum1;

        // rescale O
#pragma unroll
        for (int n = 0; n < 16; n++) {
            oacc[n][0] *= alpha0; oacc[n][1] *= alpha0;
            oacc[n][2] *= alpha1; oacc[n][3] *= alpha1;
        }
        __syncwarp();                          // P visible within warp

        // ---- O += P @ V  (A = P from per-warp smem, B = V) ----
#pragma unroll
        for (int kk = 0; kk < 16; kk++) {
            uint32_t pa[4];
            pa[0] = sPw[gid * PSTR + kk * 8 + tig];
            pa[1] = sPw[(gid + 8) * PSTR + kk * 8 + tig];
            pa[2] = sPw[gid * PSTR + kk * 8 + tig + 4];
            pa[3] = sPw[(gid + 8) * PSTR + kk * 8 + tig + 4];
            const uint32_t* vb0 = sV + (kk * 8 + tig) * VSTR;
            const uint32_t* vb1 = sV + (kk * 8 + tig + 4) * VSTR;
#pragma unroll
            for (int n = 0; n < 16; n++)
                mma_tf32(oacc[n], pa, vb0[n * 8 + gid], vb1[n * 8 + gid]);
        }
    }

    // ---- epilogue: normalize and write to g_A ----
    const int b = bh >> 2, h = bh & 3;
    const float inv0 = 1.0f / l0, inv1 = 1.0f / l1;
    float* a0 = g_A + (size_t)(b * SEQ + q0 + wq * 16 + gid) * DM + h * HD;
    float* a1 = a0 + 8 * DM;
#pragma unroll
    for (int n = 0; n < 16; n++) {
        float2 w0; w0.x = oacc[n][0] * inv0; w0.y = oacc[n][1] * inv0;
        float2 w1; w1.x = oacc[n][2] * inv1; w1.y = oacc[n][3] * inv1;
        *(float2*)&a0[n * 8 + 2 * tig] = w0;
        *(float2*)&a1[n * 8 + 2 * tig] = w1;
    }
}

// ---------------------------------------------------------------------------
extern "C" void kernel_launch(void* const* d_in, const int* in_sizes, int n_in,
                              void* d_out, int out_size)
{
    const float* query = (const float*)d_in[0];
    const float* key   = (const float*)d_in[1];
    const float* value = (const float*)d_in[2];
    const float* Wq = (const float*)d_in[3];
    const float* bq = (const float*)d_in[4];
    const float* Wk = (const float*)d_in[5];
    const float* bk = (const float*)d_in[6];
    const float* Wv = (const float*)d_in[7];
    const float* bv = (const float*)d_in[8];
    const float* Wo = (const float*)d_in[9];
    const float* bo = (const float*)d_in[10];
    float* out = (float*)d_out;

    (void)cudaFuncSetAttribute(flash_attn_mma,
                               cudaFuncAttributeMaxDynamicSharedMemorySize,
                               FLASH_SMEM);

    dim3 blk(256);
    dim3 gqkv(MROWS / 128, DM / 128, 3);     // 64 x 4 x 3
    qkv_proj_tc<<<gqkv, blk>>>(query, key, value, Wq, bq, Wk, bk, Wv, bv);

    dim3 ga(SEQ / 128, NB * NH);             // 32 x 8
    flash_attn_mma<<<ga, blk, FLASH_SMEM>>>();

    dim3 go(MROWS / 128, DM / 128);          // 64 x 4
    out_proj_tc<<<go, blk>>>(Wo, bo, out);
}

// round 14
// speedup vs baseline: 5.4333x; 1.1024x over previous
#include <cuda_runtime.h>
#include <cstdint>

#define DM   512
#define NH   4
#define HD   128
#define NB   2
#define SEQ  4096
#define MROWS (NB * SEQ)   // 8192

// Scratch (no allocations allowed)
__device__ float g_Q[NB * NH * SEQ * HD];   // [b][h][s][d]
__device__ float g_K[NB * NH * SEQ * HD];   // [b][h][s][d]
__device__ float g_V[NB * NH * SEQ * HD];   // [b][h][s][d]
__device__ float g_A[MROWS * DM];           // attention out, [b][s][h*hd]

// ---------------------------------------------------------------------------
// helpers: mma tf32 (raw fp32 bits fed as tf32 — HW uses top 19 bits),
// cp.async 16B staging.
// ---------------------------------------------------------------------------
__device__ __forceinline__ uint32_t smem_u32(const void* p) {
    uint32_t a;
    asm("{ .reg .u64 t; cvta.to.shared.u64 t, %1; cvt.u32.u64 %0, t; }"
        : "=r"(a) : "l"(p));
    return a;
}
// D(16x8,f32) += A(16x8,tf32,row) @ B(8x8,tf32,col)
__device__ __forceinline__ void mma_tf32(float* c, const uint32_t* a,
                                         uint32_t b0, uint32_t b1) {
    asm volatile(
        "mma.sync.aligned.m16n8k8.row.col.f32.tf32.tf32.f32 "
        "{%0,%1,%2,%3}, {%4,%5,%6,%7}, {%8,%9}, {%0,%1,%2,%3};"
        : "+f"(c[0]), "+f"(c[1]), "+f"(c[2]), "+f"(c[3])
        : "r"(a[0]), "r"(a[1]), "r"(a[2]), "r"(a[3]), "r"(b0), "r"(b1));
}
__device__ __forceinline__ void cp16(uint32_t saddr, const void* g) {
    asm volatile("cp.async.cg.shared.global [%0], [%1], 16;"
                 :: "r"(saddr), "l"(g));
}
#define CP_COMMIT() asm volatile("cp.async.commit_group;" ::: "memory")
#define CP_WAIT(N)  asm volatile("cp.async.wait_group %0;" :: "n"(N) : "memory")

// ---------------------------------------------------------------------------
// Tensor-core projection GEMM: C[8192,512] = X @ W^T + bias.
// CTA tile 128x128, BK=32 double-buffered via cp.async, 8 warps (4m x 2n),
// warp tile 32x64. smem stride 36 words -> conflict-free fragment loads.
// ---------------------------------------------------------------------------
#define PJ_BUF (128 * 36)                       // words per stage buffer
#define PJ_SMEM (4 * PJ_BUF * 4)                // 73728 B

__device__ __forceinline__ void pj_stage(
    const float* __restrict__ X, const float* __restrict__ W,
    uint32_t sx_u, uint32_t sw_u, int m0, int n0, int k0, int buf, int tid)
{
    const uint32_t xb = sx_u + buf * PJ_BUF * 4;
    const uint32_t wb = sw_u + buf * PJ_BUF * 4;
#pragma unroll
    for (int i = 0; i < 4; i++) {
        int idx = tid + i * 256;
        int row = idx >> 3, c4 = (idx & 7) * 4;
        cp16(xb + (row * 36 + c4) * 4, &X[(size_t)(m0 + row) * DM + k0 + c4]);
        cp16(wb + (row * 36 + c4) * 4, &W[(size_t)(n0 + row) * DM + k0 + c4]);
    }
}

__device__ __forceinline__ void gemm_tc_body(
    const float* __restrict__ X, const float* __restrict__ W,
    const float* __restrict__ bias, float* __restrict__ dst, int split,
    uint32_t* sX, uint32_t* sW)
{
    const int m0 = blockIdx.x * 128;
    const int n0 = blockIdx.y * 128;
    const int tid = threadIdx.x;
    const int w = tid >> 5, lane = tid & 31;
    const int gid = lane >> 2, tig = lane & 3;
    const int mw = (w >> 1) * 32;
    const int nw = (w & 1) * 64;
    const uint32_t sx_u = smem_u32(sX), sw_u = smem_u32(sW);

    float acc[2][8][4];
#pragma unroll
    for (int mi = 0; mi < 2; mi++)
#pragma unroll
        for (int ni = 0; ni < 8; ni++)
#pragma unroll
            for (int j = 0; j < 4; j++) acc[mi][ni][j] = 0.f;

    pj_stage(X, W, sx_u, sw_u, m0, n0, 0, 0, tid);
    CP_COMMIT();

    const int T = DM / 32;                      // 16
    for (int ki = 0; ki < T; ki++) {
        if (ki > 0) __syncthreads();
        if (ki + 1 < T) {
            pj_stage(X, W, sx_u, sw_u, m0, n0, (ki + 1) * 32, (ki + 1) & 1, tid);
            CP_COMMIT();
            CP_WAIT(1);
        } else {
            CP_WAIT(0);
        }
        __syncthreads();

        const uint32_t* bX = sX + (ki & 1) * PJ_BUF;
        const uint32_t* bW = sW + (ki & 1) * PJ_BUF;
#pragma unroll
        for (int kk = 0; kk < 4; kk++) {
            uint32_t a[2][4];
#pragma unroll
            for (int mi = 0; mi < 2; mi++) {
                const uint32_t* xr = bX + (mw + mi * 16 + gid) * 36 + kk * 8;
                a[mi][0] = xr[tig];
                a[mi][2] = xr[tig + 4];
                const uint32_t* xr2 = xr + 8 * 36;
                a[mi][1] = xr2[tig];
                a[mi][3] = xr2[tig + 4];
            }
#pragma unroll
            for (int ni = 0; ni < 8; ni++) {
                const uint32_t* wr = bW + (nw + ni * 8 + gid) * 36 + kk * 8;
                uint32_t b0 = wr[tig], b1 = wr[tig + 4];
                mma_tf32(acc[0][ni], a[0], b0, b1);
                mma_tf32(acc[1][ni], a[1], b0, b1);
            }
        }
    }

#pragma unroll
    for (int mi = 0; mi < 2; mi++) {
        int r0 = m0 + mw + mi * 16 + gid;
#pragma unroll
        for (int ni = 0; ni < 8; ni++) {
            int c = n0 + nw + ni * 8 + 2 * tig;
            float bx = bias[c], by = bias[c + 1];
            float2 v0 = make_float2(acc[mi][ni][0] + bx, acc[mi][ni][1] + by);
            float2 v1 = make_float2(acc[mi][ni][2] + bx, acc[mi][ni][3] + by);
            if (split) {
                int h = c >> 7, d = c & (HD - 1);
                int b0r = r0 >> 12, s0 = r0 & (SEQ - 1);
                *(float2*)&dst[(((size_t)(b0r * NH + h)) * SEQ + s0) * HD + d] = v0;
                int r1 = r0 + 8;
                int b1r = r1 >> 12, s1 = r1 & (SEQ - 1);
                *(float2*)&dst[(((size_t)(b1r * NH + h)) * SEQ + s1) * HD + d] = v1;
            } else {
                *(float2*)&dst[(size_t)r0 * DM + c] = v0;
                *(float2*)&dst[(size_t)(r0 + 8) * DM + c] = v1;
            }
        }
    }
}

__global__ __launch_bounds__(256, 2) void qkv_proj_tc(
    const float* __restrict__ q, const float* __restrict__ k,
    const float* __restrict__ v,
    const float* __restrict__ Wq, const float* __restrict__ bq,
    const float* __restrict__ Wk, const float* __restrict__ bk,
    const float* __restrict__ Wv, const float* __restrict__ bv)
{
    extern __shared__ uint32_t pjw[];
    uint32_t* sX = pjw;
    uint32_t* sW = pjw + 2 * PJ_BUF;
    const int z = blockIdx.z;
    const float *X, *W, *B;
    float* dst;
    if (z == 0)      { X = q; W = Wq; B = bq; dst = g_Q; }
    else if (z == 1) { X = k; W = Wk; B = bk; dst = g_K; }
    else             { X = v; W = Wv; B = bv; dst = g_V; }
    gemm_tc_body(X, W, B, dst, 1, sX, sW);
}

__global__ __launch_bounds__(256, 2) void out_proj_tc(
    const float* __restrict__ Wo, const float* __restrict__ bo,
    float* __restrict__ outp)
{
    extern __shared__ uint32_t pjw[];
    uint32_t* sX = pjw;
    uint32_t* sW = pjw + 2 * PJ_BUF;
    gemm_tc_body(g_A, Wo, bo, outp, 0, sX, sW);
}

// ---------------------------------------------------------------------------
// Flash attention (mma.sync tf32). 256 threads, 128 q-rows, 64-key tiles,
// cp.async double-buffered K/V (raw fp32 bits used as tf32 directly).
// ---------------------------------------------------------------------------
#define KT   64
#define KSTR 132
#define VSTR 136
#define PSTR 68
#define KBUF (KT * KSTR)                        // 8448 words
#define VBUF (KT * VSTR)                        // 8704 words
#define PWORDS (16 * PSTR)                      // per warp 1088 words
#define FLASH_SMEM ((2 * KBUF + 2 * VBUF + 8 * PWORDS) * 4)  // 172032 B

__device__ __forceinline__ void fa_stage(
    const float* __restrict__ Kg, const float* __restrict__ Vg,
    uint32_t sk_u, uint32_t sv_u, int k0, int buf, int tid)
{
    const uint32_t kb = sk_u + buf * KBUF * 4;
    const uint32_t vb = sv_u + buf * VBUF * 4;
#pragma unroll
    for (int i = 0; i < 8; i++) {
        int idx = tid + i * 256;
        int row = idx >> 5, c4 = (idx & 31) * 4;
        cp16(kb + (row * KSTR + c4) * 4, &Kg[(size_t)(k0 + row) * HD + c4]);
        cp16(vb + (row * VSTR + c4) * 4, &Vg[(size_t)(k0 + row) * HD + c4]);
    }
}

__global__ __launch_bounds__(256, 1) void flash_attn_mma()
{
    extern __shared__ uint32_t smw[];
    uint32_t* sK = smw;                         // [2][KT][KSTR]
    uint32_t* sV = sK + 2 * KBUF;               // [2][KT][VSTR]
    uint32_t* sP = sV + 2 * VBUF;               // 8 x [16][PSTR]

    const int tid  = threadIdx.x;
    const int wq   = tid >> 5;
    const int lane = tid & 31;
    const int gid  = lane >> 2;
    const int tig  = lane & 3;
    const int bh = blockIdx.y;
    const int q0 = blockIdx.x * 128;
    const float scale = 0.08838834764831845f;   // 1/sqrt(128)

    const float* Qg = g_Q + (size_t)bh * SEQ * HD;
    const float* Kg = g_K + (size_t)bh * SEQ * HD;
    const float* Vg = g_V + (size_t)bh * SEQ * HD;
    const uint32_t sk_u = smem_u32(sK), sv_u = smem_u32(sV);

    // prefetch tile 0 while loading Q fragments
    fa_stage(Kg, Vg, sk_u, sv_u, 0, 0, tid);
    CP_COMMIT();

    // Q fragments: rows q0+wq*16+{gid,gid+8}, 16 k-steps over d (raw bits).
    uint32_t qa[16][4];
    {
        const float* qr0 = Qg + (size_t)(q0 + wq * 16 + gid) * HD;
        const float* qr1 = qr0 + 8 * HD;
#pragma unroll
        for (int kk = 0; kk < 16; kk++) {
            qa[kk][0] = __float_as_uint(qr0[kk * 8 + tig] * scale);
            qa[kk][1] = __float_as_uint(qr1[kk * 8 + tig] * scale);
            qa[kk][2] = __float_as_uint(qr0[kk * 8 + tig + 4] * scale);
            qa[kk][3] = __float_as_uint(qr1[kk * 8 + tig + 4] * scale);
        }
    }

    uint32_t* sPw = sP + wq * PWORDS;

    float oacc[16][4];
#pragma unroll
    for (int n = 0; n < 16; n++)
#pragma unroll
        for (int j = 0; j < 4; j++) oacc[n][j] = 0.f;
    float m0 = -1e30f, m1 = -1e30f, l0 = 0.f, l1 = 0.f;

    const int T = SEQ / KT;                     // 64 tiles
    for (int t = 0; t < T; t++) {
        if (t > 0) __syncthreads();             // buffers free for overwrite
        if (t + 1 < T) {
            fa_stage(Kg, Vg, sk_u, sv_u, (t + 1) * KT, (t + 1) & 1, tid);
            CP_COMMIT();
            CP_WAIT(1);
        } else {
            CP_WAIT(0);
        }
        __syncthreads();

        const uint32_t* bK = sK + (t & 1) * KBUF;
        const uint32_t* bV = sV + (t & 1) * VBUF;

        // ---- S = Q @ K^T  (8 n-chunks of 8 keys, 16 k-steps over d) ----
        float sacc[8][4];
#pragma unroll
        for (int n = 0; n < 8; n++) {
            sacc[n][0] = sacc[n][1] = sacc[n][2] = sacc[n][3] = 0.f;
            const uint32_t* kb = bK + (n * 8 + gid) * KSTR;
#pragma unroll
            for (int kk = 0; kk < 16; kk++)
                mma_tf32(sacc[n], qa[kk], kb[kk * 8 + tig], kb[kk * 8 + tig + 4]);
        }

        // ---- online softmax ----
        float mx0 = m0, mx1 = m1;
#pragma unroll
        for (int n = 0; n < 8; n++) {
            mx0 = fmaxf(mx0, fmaxf(sacc[n][0], sacc[n][1]));
            mx1 = fmaxf(mx1, fmaxf(sacc[n][2], sacc[n][3]));
        }
        mx0 = fmaxf(mx0, __shfl_xor_sync(0xffffffffu, mx0, 1));
        mx0 = fmaxf(mx0, __shfl_xor_sync(0xffffffffu, mx0, 2));
        mx1 = fmaxf(mx1, __shfl_xor_sync(0xffffffffu, mx1, 1));
        mx1 = fmaxf(mx1, __shfl_xor_sync(0xffffffffu, mx1, 2));

        const float alpha0 = __expf(m0 - mx0);
        const float alpha1 = __expf(m1 - mx1);
        m0 = mx0; m1 = mx1;

        float sum0 = 0.f, sum1 = 0.f;
#pragma unroll
        for (int n = 0; n < 8; n++) {
            float p00 = __expf(sacc[n][0] - mx0);
            float p01 = __expf(sacc[n][1] - mx0);
            float p10 = __expf(sacc[n][2] - mx1);
            float p11 = __expf(sacc[n][3] - mx1);
            sum0 += p00 + p01;
            sum1 += p10 + p11;
            uint2 w0; w0.x = __float_as_uint(p00); w0.y = __float_as_uint(p01);
            uint2 w1; w1.x = __float_as_uint(p10); w1.y = __float_as_uint(p11);
            *(uint2*)&sPw[gid * PSTR + n * 8 + 2 * tig] = w0;
            *(uint2*)&sPw[(gid + 8) * PSTR + n * 8 + 2 * tig] = w1;
        }
        sum0 += __shfl_xor_sync(0xffffffffu, sum0, 1);
        sum0 += __shfl_xor_sync(0xffffffffu, sum0, 2);
        sum1 += __shfl_xor_sync(0xffffffffu, sum1, 1);
        sum1 += __shfl_xor_sync(0xffffffffu, sum1, 2);
        l0 = l0 * alpha0 + sum0;
        l1 = l1 * alpha1 + sum1;

#pragma unroll
        for (int n = 0; n < 16; n++) {
            oacc[n][0] *= alpha0; oacc[n][1] *= alpha0;
            oacc[n][2] *= alpha1; oacc[n][3] *= alpha1;
        }
        __syncwarp();                           // P visible within warp

        // ---- O += P @ V  (8 k-steps over keys) ----
#pragma unroll
        for (int kk = 0; kk < 8; kk++) {
            uint32_t pa[4];
            pa[0] = sPw[gid * PSTR + kk * 8 + tig];
            pa[1] = sPw[(gid + 8) * PSTR + kk * 8 + tig];
            pa[2] = sPw[gid * PSTR + kk * 8 + tig + 4];
            pa[3] = sPw[(gid + 8) * PSTR + kk * 8 + tig + 4];
            const uint32_t* vb0 = bV + (kk * 8 + tig) * VSTR;
            const uint32_t* vb1 = bV + (kk * 8 + tig + 4) * VSTR;
#pragma unroll
            for (int n = 0; n < 16; n++)
                mma_tf32(oacc[n], pa, vb0[n * 8 + gid], vb1[n * 8 + gid]);
        }
    }

    // ---- epilogue ----
    const int b = bh >> 2, h = bh & 3;
    const float inv0 = 1.0f / l0, inv1 = 1.0f / l1;
    float* a0 = g_A + (size_t)(b * SEQ + q0 + wq * 16 + gid) * DM + h * HD;
    float* a1 = a0 + 8 * DM;
#pragma unroll
    for (int n = 0; n < 16; n++) {
        float2 w0; w0.x = oacc[n][0] * inv0; w0.y = oacc[n][1] * inv0;
        float2 w1; w1.x = oacc[n][2] * inv1; w1.y = oacc[n][3] * inv1;
        *(float2*)&a0[n * 8 + 2 * tig] = w0;
        *(float2*)&a1[n * 8 + 2 * tig] = w1;
    }
}

// ---------------------------------------------------------------------------
extern "C" void kernel_launch(void* const* d_in, const int* in_sizes, int n_in,
                              void* d_out, int out_size)
{
    const float* query = (const float*)d_in[0];
    const float* key   = (const float*)d_in[1];
    const float* value = (const float*)d_in[2];
    const float* Wq = (const float*)d_in[3];
    const float* bq = (const float*)d_in[4];
    const float* Wk = (const float*)d_in[5];
    const float* bk = (const float*)d_in[6];
    const float* Wv = (const float*)d_in[7];
    const float* bv = (const float*)d_in[8];
    const float* Wo = (const float*)d_in[9];
    const float* bo = (const float*)d_in[10];
    float* out = (float*)d_out;

    (void)cudaFuncSetAttribute(flash_attn_mma,
                               cudaFuncAttributeMaxDynamicSharedMemorySize,
                               FLASH_SMEM);
    (void)cudaFuncSetAttribute(qkv_proj_tc,
                               cudaFuncAttributeMaxDynamicSharedMemorySize,
                               PJ_SMEM);
    (void)cudaFuncSetAttribute(out_proj_tc,
                               cudaFuncAttributeMaxDynamicSharedMemorySize,
                               PJ_SMEM);

    dim3 blk(256);
    dim3 gqkv(MROWS / 128, DM / 128, 3);     // 64 x 4 x 3
    qkv_proj_tc<<<gqkv, blk, PJ_SMEM>>>(query, key, value,
                                        Wq, bq, Wk, bk, Wv, bv);

    dim3 ga(SEQ / 128, NB * NH);             // 32 x 8
    flash_attn_mma<<<ga, blk, FLASH_SMEM>>>();

    dim3 go(MROWS / 128, DM / 128);          // 64 x 4
    out_proj_tc<<<go, blk, PJ_SMEM>>>(Wo, bo, out);
}